// round 1
// baseline (speedup 1.0000x reference)
#include <cuda_runtime.h>
#include <cstdint>
#include <cstddef>

#define HD 1024
#define BB 32
#define SS 2048
#define VV 32000
#define G3 3072
#define SC 64          // attention rows per chunk
#define NCH (SS/SC)    // 32 chunks per batch row
#define SK 8           // k-split for small GEMMs

// ---------------- scratch (device globals; no allocs allowed) ----------------
__device__ float g_rnn_in[BB*2*HD];
__device__ float g_pgi[SK*BB*G3];
__device__ float g_pgh[SK*BB*G3];
__device__ float g_h0[BB*HD];
__device__ float g_h1[BB*HD];
__device__ float g_pq[SK*BB*HD];
__device__ float g_q[BB*HD];
__device__ float g_cb[BB];
__device__ float g_scores[BB*SS];
__device__ float g_pm[BB*NCH];
__device__ float g_pl[BB*NCH];
__device__ float g_pctx[BB*NCH*HD];
__device__ float g_MZ[BB*2];
__device__ float g_cat[BB*2*HD];
__device__ float g_logits[BB*VV];

// ---------------- reductions ----------------
__device__ __forceinline__ float blockReduceSum256(float v) {
    __shared__ float s[8];
    int lane = threadIdx.x & 31, w = threadIdx.x >> 5;
    __syncthreads();
    #pragma unroll
    for (int o = 16; o > 0; o >>= 1) v += __shfl_xor_sync(0xffffffffu, v, o);
    if (lane == 0) s[w] = v;
    __syncthreads();
    if (w == 0) {
        float x = (lane < 8) ? s[lane] : 0.0f;
        #pragma unroll
        for (int o = 4; o > 0; o >>= 1) x += __shfl_xor_sync(0xffffffffu, x, o);
        if (lane == 0) s[0] = x;
    }
    __syncthreads();
    return s[0];
}

__device__ __forceinline__ float blockReduceMax256(float v) {
    __shared__ float s[8];
    int lane = threadIdx.x & 31, w = threadIdx.x >> 5;
    __syncthreads();
    #pragma unroll
    for (int o = 16; o > 0; o >>= 1) v = fmaxf(v, __shfl_xor_sync(0xffffffffu, v, o));
    if (lane == 0) s[w] = v;
    __syncthreads();
    if (w == 0) {
        float x = (lane < 8) ? s[lane] : -3.4e38f;
        #pragma unroll
        for (int o = 4; o > 0; o >>= 1) x = fmaxf(x, __shfl_xor_sync(0xffffffffu, x, o));
        if (lane == 0) s[0] = x;
    }
    __syncthreads();
    return s[0];
}

// ---------------- 1: embedding + concat ----------------
__global__ void k_embed(const int* __restrict__ ids, const float* __restrict__ emb,
                        const float* __restrict__ lastctx) {
    int b = blockIdx.x, t = threadIdx.x;  // 256 threads
    const float4* e = (const float4*)(emb + (size_t)ids[b] * HD);
    float4* dst = (float4*)(g_rnn_in + (size_t)b * 2 * HD);
    dst[t]       = e[t];
    dst[256 + t] = ((const float4*)(lastctx + (size_t)b * HD))[t];
}

// ---------------- 2: generic skinny GEMM  C[b,n] = sum_k X[b,k]*W(n,k) ----------------
// wt==0: W is [N][K] row-major.  wt==1: W(n,k) = Wglob[k*N + n] (transposed access).
// gridDim.y = SK partial k-splits (write to C[sk][B][N], no bias) or 1 (bias applied).
__global__ __launch_bounds__(128) void k_gemm(
    const float* __restrict__ X, const float* __restrict__ W,
    const float* __restrict__ bias, float* __restrict__ C,
    int N, int K, int wt, int kchunk)
{
    const int KT = 64;
    __shared__ float Xs[KT][32];
    __shared__ float Ws[128][KT + 1];
    int n0 = blockIdx.x * 128;
    int kb = blockIdx.y * kchunk;
    int ke = kb + kchunk;
    int tid = threadIdx.x;
    int tx = tid & 7;       // batch group (4 b each)
    int ty = tid >> 3;      // n group (8 n each)

    unsigned long long acc[8][2];
    #pragma unroll
    for (int j = 0; j < 8; j++) { acc[j][0] = 0ull; acc[j][1] = 0ull; }

    for (int k0 = kb; k0 < ke; k0 += KT) {
        #pragma unroll 4
        for (int i = tid; i < KT * 32; i += 128) {
            int k = i >> 5, b = i & 31;
            Xs[k][b] = X[(size_t)b * K + k0 + k];
        }
        if (!wt) {
            const float4* wr = (const float4*)(W + (size_t)(n0 + tid) * K + k0);
            #pragma unroll
            for (int k4 = 0; k4 < KT / 4; k4++) {
                float4 w4 = wr[k4];
                Ws[tid][k4 * 4 + 0] = w4.x; Ws[tid][k4 * 4 + 1] = w4.y;
                Ws[tid][k4 * 4 + 2] = w4.z; Ws[tid][k4 * 4 + 3] = w4.w;
            }
        } else {
            #pragma unroll 4
            for (int i = tid; i < 128 * KT; i += 128) {
                int n = i & 127, k = i >> 7;
                Ws[n][k] = W[(size_t)(k0 + k) * N + n0 + n];
            }
        }
        __syncthreads();
        #pragma unroll 8
        for (int k = 0; k < KT; k++) {
            float4 x4 = *(const float4*)&Xs[k][tx * 4];
            unsigned long long x01, x23;
            asm("mov.b64 %0, {%1, %2};" : "=l"(x01) : "f"(x4.x), "f"(x4.y));
            asm("mov.b64 %0, {%1, %2};" : "=l"(x23) : "f"(x4.z), "f"(x4.w));
            #pragma unroll
            for (int j = 0; j < 8; j++) {
                float w = Ws[ty * 8 + j][k];
                unsigned long long w2;
                asm("mov.b64 %0, {%1, %1};" : "=l"(w2) : "f"(w));
                asm("fma.rn.f32x2 %0, %1, %2, %0;" : "+l"(acc[j][0]) : "l"(x01), "l"(w2));
                asm("fma.rn.f32x2 %0, %1, %2, %0;" : "+l"(acc[j][1]) : "l"(x23), "l"(w2));
            }
        }
        __syncthreads();
    }

    size_t cbase = (gridDim.y > 1) ? (size_t)blockIdx.y * BB * N : 0;
    #pragma unroll
    for (int j = 0; j < 8; j++) {
        int n = n0 + ty * 8 + j;
        float bv = (bias != nullptr && gridDim.y == 1) ? bias[n] : 0.0f;
        float a0, a1, a2, a3;
        asm("mov.b64 {%0, %1}, %2;" : "=f"(a0), "=f"(a1) : "l"(acc[j][0]));
        asm("mov.b64 {%0, %1}, %2;" : "=f"(a2), "=f"(a3) : "l"(acc[j][1]));
        C[cbase + (size_t)(tx * 4 + 0) * N + n] = a0 + bv;
        C[cbase + (size_t)(tx * 4 + 1) * N + n] = a1 + bv;
        C[cbase + (size_t)(tx * 4 + 2) * N + n] = a2 + bv;
        C[cbase + (size_t)(tx * 4 + 3) * N + n] = a3 + bv;
    }
}

// ---------------- 3: GRU gate combine (sums k-split partials) ----------------
__global__ void k_combine(const float* __restrict__ bih, const float* __restrict__ bhh,
                          const float* __restrict__ hprev, float* __restrict__ hout,
                          float* __restrict__ hid_out) {
    int idx = blockIdx.x * 256 + threadIdx.x;   // BB*HD = 32768
    int b = idx >> 10, h = idx & 1023;
    float gir = bih[h], giz = bih[HD + h], gin = bih[2 * HD + h];
    float ghr = bhh[h], ghz = bhh[HD + h], ghn = bhh[2 * HD + h];
    #pragma unroll
    for (int s = 0; s < SK; s++) {
        const float* pi = g_pgi + ((size_t)s * BB + b) * G3;
        const float* ph = g_pgh + ((size_t)s * BB + b) * G3;
        gir += pi[h]; giz += pi[HD + h]; gin += pi[2 * HD + h];
        ghr += ph[h]; ghz += ph[HD + h]; ghn += ph[2 * HD + h];
    }
    float r = 1.0f / (1.0f + expf(-(gir + ghr)));
    float z = 1.0f / (1.0f + expf(-(giz + ghz)));
    float n = tanhf(gin + r * ghn);
    float hp = hprev[idx];
    float hn = (1.0f - z) * n + z * hp;
    hout[idx] = hn;
    hid_out[idx] = hn;
}

// ---------------- 4: finalize q partials + cb = b_attn . h1 ----------------
__global__ void k_qfin(const float* __restrict__ b_attn) {
    int b = blockIdx.x, t = threadIdx.x;   // 256 threads, 4 floats each
    float4 acc = {0, 0, 0, 0};
    #pragma unroll
    for (int s = 0; s < SK; s++) {
        float4 v = *(const float4*)(g_pq + ((size_t)s * BB + b) * HD + t * 4);
        acc.x += v.x; acc.y += v.y; acc.z += v.z; acc.w += v.w;
    }
    *(float4*)(g_q + (size_t)b * HD + t * 4) = acc;
    float4 ba = *(const float4*)(b_attn + t * 4);
    float4 hv = *(const float4*)(g_h1 + (size_t)b * HD + t * 4);
    float p = ba.x * hv.x + ba.y * hv.y + ba.z * hv.z + ba.w * hv.w;
    p = blockReduceSum256(p);
    if (t == 0) g_cb[b] = p;
}

// ---------------- 5: flash-style scores + partial softmax + partial context ----------------
__global__ __launch_bounds__(256) void k_scores_ctx(const float* __restrict__ enc) {
    int b = blockIdx.y, ch = blockIdx.x;
    int s0 = ch * SC;
    __shared__ float qs[HD];
    __shared__ float ps[SC];
    int t = threadIdx.x;
    ((float4*)qs)[t] = ((const float4*)(g_q + (size_t)b * HD))[t];
    __syncthreads();
    int w = t >> 5, lane = t & 31;
    float cb = g_cb[b];
    // phase 1: 8 warps x 8 rows -> scores
    #pragma unroll
    for (int rr = 0; rr < 8; rr++) {
        int s = s0 + rr * 8 + w;
        const float4* e = (const float4*)(enc + ((size_t)b * SS + s) * HD);
        float sum = 0.0f;
        #pragma unroll
        for (int i = 0; i < 8; i++) {
            float4 ev = e[lane + i * 32];
            float4 qv = ((const float4*)qs)[lane + i * 32];
            sum += ev.x * qv.x + ev.y * qv.y + ev.z * qv.z + ev.w * qv.w;
        }
        #pragma unroll
        for (int o = 16; o > 0; o >>= 1) sum += __shfl_xor_sync(0xffffffffu, sum, o);
        if (lane == 0) {
            float v = sum + cb;
            ps[rr * 8 + w] = v;
            g_scores[(size_t)b * SS + s] = v;
        }
    }
    __syncthreads();
    // phase 2: chunk-local softmax stats (warp 0)
    if (t < 32) {
        float v0 = ps[t], v1 = ps[t + 32];
        float m = fmaxf(v0, v1);
        #pragma unroll
        for (int o = 16; o > 0; o >>= 1) m = fmaxf(m, __shfl_xor_sync(0xffffffffu, m, o));
        float p0 = expf(v0 - m), p1 = expf(v1 - m);
        float l = p0 + p1;
        #pragma unroll
        for (int o = 16; o > 0; o >>= 1) l += __shfl_xor_sync(0xffffffffu, l, o);
        ps[t] = p0; ps[t + 32] = p1;
        if (t == 0) { g_pm[b * NCH + ch] = m; g_pl[b * NCH + ch] = l; }
    }
    __syncthreads();
    // phase 3: partial context (chunk re-read hits L2)
    float4 acc = {0, 0, 0, 0};
    const float* eb = enc + ((size_t)b * SS + s0) * HD;
    #pragma unroll 4
    for (int s = 0; s < SC; s++) {
        float p = ps[s];
        float4 ev = *(const float4*)(eb + (size_t)s * HD + t * 4);
        acc.x += p * ev.x; acc.y += p * ev.y; acc.z += p * ev.z; acc.w += p * ev.w;
    }
    *(float4*)(g_pctx + ((size_t)(b * NCH + ch)) * HD + t * 4) = acc;
}

// ---------------- 6: combine attention partials -> context, cat=[h1,ctx] ----------------
__global__ __launch_bounds__(256) void k_att_reduce(float* __restrict__ ctx_out) {
    int b = blockIdx.x, t = threadIdx.x;
    __shared__ float wc[NCH];
    __shared__ float MZ[2];
    if (t < 32) {
        float m = g_pm[b * NCH + t];
        float M = m;
        #pragma unroll
        for (int o = 16; o > 0; o >>= 1) M = fmaxf(M, __shfl_xor_sync(0xffffffffu, M, o));
        float e = expf(m - M);
        float z = g_pl[b * NCH + t] * e;
        #pragma unroll
        for (int o = 16; o > 0; o >>= 1) z += __shfl_xor_sync(0xffffffffu, z, o);
        wc[t] = e;
        if (t == 0) { MZ[0] = M; MZ[1] = z; g_MZ[b * 2] = M; g_MZ[b * 2 + 1] = z; }
    }
    __syncthreads();
    float invZ = 1.0f / MZ[1];
    float4 acc = {0, 0, 0, 0};
    #pragma unroll 4
    for (int c = 0; c < NCH; c++) {
        float s = wc[c];
        float4 v = *(const float4*)(g_pctx + ((size_t)(b * NCH + c)) * HD + t * 4);
        acc.x += s * v.x; acc.y += s * v.y; acc.z += s * v.z; acc.w += s * v.w;
    }
    acc.x *= invZ; acc.y *= invZ; acc.z *= invZ; acc.w *= invZ;
    *(float4*)(ctx_out + (size_t)b * HD + t * 4) = acc;
    *(float4*)(g_cat + (size_t)b * 2 * HD + HD + t * 4) = acc;
    float4 h1v = *(const float4*)(g_h1 + (size_t)b * HD + t * 4);
    *(float4*)(g_cat + (size_t)b * 2 * HD + t * 4) = h1v;
}

// ---------------- 7: normalized attention weights ----------------
__global__ void k_attn_out(float* __restrict__ attn_out) {
    int idx = blockIdx.x * 256 + threadIdx.x;   // BB*SS
    int b = idx >> 11;
    float M = g_MZ[b * 2], Z = g_MZ[b * 2 + 1];
    attn_out[idx] = expf(g_scores[idx] - M) / Z;
}

// ---------------- 8: output softmax over V ----------------
__global__ __launch_bounds__(256) void k_softmax_out(float* __restrict__ out) {
    int b = blockIdx.x, t = threadIdx.x;
    const float* l = g_logits + (size_t)b * VV;
    float* o = out + (size_t)b * VV;
    float m = -3.4e38f;
    for (int i = t; i < VV; i += 256) m = fmaxf(m, l[i]);
    m = blockReduceMax256(m);
    float s = 0.0f;
    for (int i = t; i < VV; i += 256) { float e = expf(l[i] - m); o[i] = e; s += e; }
    s = blockReduceSum256(s);
    float inv = 1.0f / s;
    for (int i = t; i < VV; i += 256) o[i] *= inv;
}

// ---------------- launch ----------------
extern "C" void kernel_launch(void* const* d_in, const int* in_sizes, int n_in,
                              void* d_out, int out_size) {
    const int*   ids   = (const int*)d_in[0];
    const float* lctx  = (const float*)d_in[1];
    const float* hid   = (const float*)d_in[2];
    const float* enc   = (const float*)d_in[3];
    const float* emb   = (const float*)d_in[4];
    const float* Wattn = (const float*)d_in[5];
    const float* battn = (const float*)d_in[6];
    const float* Wih0  = (const float*)d_in[7];
    const float* Whh0  = (const float*)d_in[8];
    const float* bih0  = (const float*)d_in[9];
    const float* bhh0  = (const float*)d_in[10];
    const float* Wih1  = (const float*)d_in[11];
    const float* Whh1  = (const float*)d_in[12];
    const float* bih1  = (const float*)d_in[13];
    const float* bhh1  = (const float*)d_in[14];
    const float* Wout  = (const float*)d_in[15];
    const float* bout  = (const float*)d_in[16];

    float* out = (float*)d_out;
    float* out_probs = out;                                 // [B,V]
    float* out_ctx   = out + (size_t)BB * VV;               // [1,B,H]
    float* out_hid   = out_ctx + (size_t)BB * HD;           // [L,B,H]
    float* out_attn  = out_hid + (size_t)2 * BB * HD;       // [B,1,S]

    float *p_rnn_in, *p_pgi, *p_pgh, *p_h0, *p_h1, *p_pq, *p_cat, *p_logits;
    cudaGetSymbolAddress((void**)&p_rnn_in, g_rnn_in);
    cudaGetSymbolAddress((void**)&p_pgi,    g_pgi);
    cudaGetSymbolAddress((void**)&p_pgh,    g_pgh);
    cudaGetSymbolAddress((void**)&p_h0,     g_h0);
    cudaGetSymbolAddress((void**)&p_h1,     g_h1);
    cudaGetSymbolAddress((void**)&p_pq,     g_pq);
    cudaGetSymbolAddress((void**)&p_cat,    g_cat);
    cudaGetSymbolAddress((void**)&p_logits, g_logits);

    // 1. embedding + concat -> rnn_in [B, 2H]
    k_embed<<<BB, 256>>>(ids, emb, lctx);
    // 2. GRU layer 0 gates (k-split partials)
    k_gemm<<<dim3(G3 / 128, SK), 128>>>(p_rnn_in, Wih0, nullptr, p_pgi, G3, 2 * HD, 0, (2 * HD) / SK);
    k_gemm<<<dim3(G3 / 128, SK), 128>>>(hid,      Whh0, nullptr, p_pgh, G3, HD,     0, HD / SK);
    k_combine<<<(BB * HD) / 256, 256>>>(bih0, bhh0, hid, p_h0, out_hid);
    // 3. GRU layer 1
    k_gemm<<<dim3(G3 / 128, SK), 128>>>(p_h0,         Wih1, nullptr, p_pgi, G3, HD, 0, HD / SK);
    k_gemm<<<dim3(G3 / 128, SK), 128>>>(hid + BB * HD, Whh1, nullptr, p_pgh, G3, HD, 0, HD / SK);
    k_combine<<<(BB * HD) / 256, 256>>>(bih1, bhh1, hid + BB * HD, p_h1, out_hid + BB * HD);
    // 4. q = h1 @ W_attn  (transposed W access), then finalize + cb
    k_gemm<<<dim3(HD / 128, SK), 128>>>(p_h1, Wattn, nullptr, p_pq, HD, HD, 1, HD / SK);
    k_qfin<<<BB, 256>>>(battn);
    // 5. attention: scores + partial softmax + partial context (one DRAM pass over enc)
    k_scores_ctx<<<dim3(NCH, BB), 256>>>(enc);
    k_att_reduce<<<BB, 256>>>(out_ctx);
    k_attn_out<<<(BB * SS) / 256, 256>>>(out_attn);
    // 6. logits GEMM + output softmax
    k_gemm<<<dim3(VV / 128, 1), 128>>>(p_cat, Wout, bout, p_logits, VV, 2 * HD, 0, 2 * HD);
    k_softmax_out<<<BB, 256>>>(out_probs);
}

// round 2
// speedup vs baseline: 1.5641x; 1.5641x over previous
#include <cuda_runtime.h>
#include <cstdint>
#include <cstddef>

#define HD 1024
#define BB 32
#define SS 2048
#define VV 32000
#define G3 3072
#define SC 64          // attention rows per chunk
#define NCH (SS/SC)    // 32
#define SK 8           // k-split for small GEMMs
#define KT 64          // GEMM k-tile
#define LBLK (VV/128)  // 250 logits blocks

// ---------------- scratch ----------------
__device__ float g_xT[2*HD*BB];      // rnn_in transposed [2H][B]
__device__ float g_hT[2*HD*BB];      // hidden transposed [L][H][B]
__device__ float g_h0T[HD*BB];
__device__ float g_h1[BB*HD];
__device__ float g_h1T[HD*BB];
__device__ float g_catT[2*HD*BB];
__device__ float g_pgi[SK*BB*G3];
__device__ float g_pgh[SK*BB*G3];
__device__ float g_pq[SK*BB*HD];
__device__ float g_q[BB*HD];
__device__ float g_cb[BB];
__device__ float g_scores[BB*SS];
__device__ float g_pm[BB*NCH];
__device__ float g_pl[BB*NCH];
__device__ float g_pctx[BB*NCH*HD];
__device__ float g_MZ[BB*2];
__device__ float g_logits[BB*VV];
__device__ float g_lm[LBLK*BB];
__device__ float g_ls[LBLK*BB];
__device__ float g_MZl[BB*2];

// ---------------- reductions ----------------
__device__ __forceinline__ float blockReduceSum256(float v) {
    __shared__ float s[8];
    int lane = threadIdx.x & 31, w = threadIdx.x >> 5;
    __syncthreads();
    #pragma unroll
    for (int o = 16; o > 0; o >>= 1) v += __shfl_xor_sync(0xffffffffu, v, o);
    if (lane == 0) s[w] = v;
    __syncthreads();
    if (w == 0) {
        float x = (lane < 8) ? s[lane] : 0.0f;
        #pragma unroll
        for (int o = 4; o > 0; o >>= 1) x += __shfl_xor_sync(0xffffffffu, x, o);
        if (lane == 0) s[0] = x;
    }
    __syncthreads();
    return s[0];
}

// ---------------- 1: embedding + concat -> xT (k-major) ----------------
__global__ void k_embed(const int* __restrict__ ids, const float* __restrict__ emb,
                        const float* __restrict__ lastctx) {
    int b = blockIdx.x, t = threadIdx.x;  // 256 threads
    float4 e = ((const float4*)(emb + (size_t)ids[b] * HD))[t];
    float4 c = ((const float4*)(lastctx + (size_t)b * HD))[t];
    int h = t * 4;
    g_xT[(h+0)*BB + b] = e.x; g_xT[(h+1)*BB + b] = e.y;
    g_xT[(h+2)*BB + b] = e.z; g_xT[(h+3)*BB + b] = e.w;
    g_xT[(HD+h+0)*BB + b] = c.x; g_xT[(HD+h+1)*BB + b] = c.y;
    g_xT[(HD+h+2)*BB + b] = c.z; g_xT[(HD+h+3)*BB + b] = c.w;
}

// ---------------- 2: transpose hidden [L,B,H] -> [L,H,B] ----------------
__global__ void k_transpose(const float* __restrict__ in) {
    __shared__ float s[32][33];
    int l = blockIdx.y, h0 = blockIdx.x * 32;
    int tx = threadIdx.x, ty = threadIdx.y;
    s[ty][tx] = in[(size_t)l * BB * HD + (size_t)ty * HD + h0 + tx];
    __syncthreads();
    g_hT[(size_t)l * HD * BB + (size_t)(h0 + ty) * BB + tx] = s[tx][ty];
}

// ---------------- 3: skinny GEMM  C[b,n] = sum_k XT[k][b]*W(n,k) ----------------
// XT is k-major [K][32]. wt==0: W row-major [N][K]. wt==1: W(n,k)=W[k*N+n].
// f32x2 lanes pack (even-k, odd-k) partial sums -> no packing movs.
// Ws rows are chunk-XOR-swizzled for conflict-free LDS128.
__global__ __launch_bounds__(128) void k_gemm(
    const float* __restrict__ XT, const float* __restrict__ W,
    const float* __restrict__ bias, float* __restrict__ C,
    int N, int K, int wt, int kchunk, int stats,
    float* __restrict__ lm, float* __restrict__ ls)
{
    __shared__ float Xs[32*66];     // [b][66]
    __shared__ float Ws[128*64];    // [n][64], chunks swizzled by (n>>3)
    int tid = threadIdx.x;
    int tn = tid & 15;              // n-group (8 n each)
    int tb = tid >> 4;              // b-group (4 b each)
    int n0 = blockIdx.x * 128;
    int kb = blockIdx.y * kchunk;

    unsigned long long acc[4][8];
    #pragma unroll
    for (int bi = 0; bi < 4; bi++)
        #pragma unroll
        for (int j = 0; j < 8; j++) acc[bi][j] = 0ull;

    for (int k0 = kb; k0 < kb + kchunk; k0 += KT) {
        // X fill: XT chunk is linear; scatter-transpose to [b][k]
        #pragma unroll
        for (int r = 0; r < 16; r++) {
            int i = r * 128 + tid;
            int k = i >> 5, b = i & 31;
            Xs[b * 66 + k] = XT[(size_t)k0 * 32 + i];
        }
        if (!wt) {
            #pragma unroll
            for (int r = 0; r < 16; r++) {
                int i = r * 128 + tid;
                int n = i >> 4;        // 0..127
                int c = i & 15;        // k-chunk
                float4 w4 = *(const float4*)(W + (size_t)(n0 + n) * K + k0 + c * 4);
                int cs = c ^ ((n >> 3) & 15);
                *(float4*)&Ws[n * 64 + cs * 4] = w4;
            }
        } else {
            for (int i = tid; i < 128 * KT; i += 128) {
                int n = i & 127, k = i >> 7;
                int cs = (k >> 2) ^ ((n >> 3) & 15);
                Ws[n * 64 + cs * 4 + (k & 3)] = W[(size_t)(k0 + k) * N + n0 + n];
            }
        }
        __syncthreads();
        #pragma unroll 4
        for (int kk = 0; kk < KT; kk += 4) {
            int csw = ((kk >> 2) ^ tn) * 4;
            unsigned long long x01[4], x23[4];
            #pragma unroll
            for (int bi = 0; bi < 4; bi++) {
                const float* xp = &Xs[(tb * 4 + bi) * 66 + kk];
                x01[bi] = *(const unsigned long long*)(xp);
                x23[bi] = *(const unsigned long long*)(xp + 2);
            }
            #pragma unroll
            for (int j = 0; j < 8; j++) {
                ulonglong2 w = *(const ulonglong2*)&Ws[(tn * 8 + j) * 64 + csw];
                #pragma unroll
                for (int bi = 0; bi < 4; bi++)
                    asm("fma.rn.f32x2 %0, %1, %2, %0;" : "+l"(acc[bi][j]) : "l"(x01[bi]), "l"(w.x));
                #pragma unroll
                for (int bi = 0; bi < 4; bi++)
                    asm("fma.rn.f32x2 %0, %1, %2, %0;" : "+l"(acc[bi][j]) : "l"(x23[bi]), "l"(w.y));
            }
        }
        __syncthreads();
    }

    size_t cbase = (gridDim.y > 1) ? (size_t)blockIdx.y * BB * N : 0;
    float v[4][8];
    #pragma unroll
    for (int j = 0; j < 8; j++) {
        float bv = (bias != nullptr && gridDim.y == 1) ? bias[n0 + tn * 8 + j] : 0.0f;
        #pragma unroll
        for (int bi = 0; bi < 4; bi++) {
            float lo, hi;
            asm("mov.b64 {%0, %1}, %2;" : "=f"(lo), "=f"(hi) : "l"(acc[bi][j]));
            v[bi][j] = lo + hi + bv;
        }
    }
    #pragma unroll
    for (int bi = 0; bi < 4; bi++) {
        size_t off = cbase + (size_t)(tb * 4 + bi) * N + n0 + tn * 8;
        float4 s0 = make_float4(v[bi][0], v[bi][1], v[bi][2], v[bi][3]);
        float4 s1 = make_float4(v[bi][4], v[bi][5], v[bi][6], v[bi][7]);
        *(float4*)(C + off) = s0;
        *(float4*)(C + off + 4) = s1;
    }
    if (stats) {
        #pragma unroll
        for (int bi = 0; bi < 4; bi++) {
            float m = v[bi][0];
            #pragma unroll
            for (int j = 1; j < 8; j++) m = fmaxf(m, v[bi][j]);
            float sum = 0.0f;
            #pragma unroll
            for (int j = 0; j < 8; j++) sum += expf(v[bi][j] - m);
            #pragma unroll
            for (int o = 1; o < 16; o <<= 1) {
                float mo = __shfl_xor_sync(0xffffffffu, m, o);
                float so = __shfl_xor_sync(0xffffffffu, sum, o);
                float M = fmaxf(m, mo);
                sum = sum * expf(m - M) + so * expf(mo - M);
                m = M;
            }
            if (tn == 0) {
                lm[blockIdx.x * BB + tb * 4 + bi] = m;
                ls[blockIdx.x * BB + tb * 4 + bi] = sum;
            }
        }
    }
}

// ---------------- 4: GRU gate combine ----------------
__global__ void k_combine(const float* __restrict__ bih, const float* __restrict__ bhh,
                          const float* __restrict__ hprev, float* __restrict__ houtT,
                          float* __restrict__ hid_out, float* __restrict__ hout_row) {
    int idx = blockIdx.x * 256 + threadIdx.x;   // BB*HD
    int b = idx >> 10, h = idx & 1023;
    float gir = bih[h], giz = bih[HD + h], gin = bih[2 * HD + h];
    float ghr = bhh[h], ghz = bhh[HD + h], ghn = bhh[2 * HD + h];
    #pragma unroll
    for (int s = 0; s < SK; s++) {
        const float* pi = g_pgi + ((size_t)s * BB + b) * G3;
        const float* ph = g_pgh + ((size_t)s * BB + b) * G3;
        gir += pi[h]; giz += pi[HD + h]; gin += pi[2 * HD + h];
        ghr += ph[h]; ghz += ph[HD + h]; ghn += ph[2 * HD + h];
    }
    float r = 1.0f / (1.0f + expf(-(gir + ghr)));
    float z = 1.0f / (1.0f + expf(-(giz + ghz)));
    float n = tanhf(gin + r * ghn);
    float hn = (1.0f - z) * n + z * hprev[idx];
    houtT[h * BB + b] = hn;
    hid_out[idx] = hn;
    if (hout_row) hout_row[idx] = hn;
}

// ---------------- 5: finalize q partials + cb = b_attn . h1 ----------------
__global__ void k_qfin(const float* __restrict__ b_attn) {
    int b = blockIdx.x, t = threadIdx.x;
    float4 acc = {0, 0, 0, 0};
    #pragma unroll
    for (int s = 0; s < SK; s++) {
        float4 v = *(const float4*)(g_pq + ((size_t)s * BB + b) * HD + t * 4);
        acc.x += v.x; acc.y += v.y; acc.z += v.z; acc.w += v.w;
    }
    *(float4*)(g_q + (size_t)b * HD + t * 4) = acc;
    float4 ba = *(const float4*)(b_attn + t * 4);
    float4 hv = *(const float4*)(g_h1 + (size_t)b * HD + t * 4);
    float p = ba.x * hv.x + ba.y * hv.y + ba.z * hv.z + ba.w * hv.w;
    p = blockReduceSum256(p);
    if (t == 0) g_cb[b] = p;
}

// ---------------- 6: flash-style scores + partial softmax + partial context ----------------
__global__ __launch_bounds__(256) void k_scores_ctx(const float* __restrict__ enc) {
    int b = blockIdx.y, ch = blockIdx.x;
    int s0 = ch * SC;
    __shared__ float qs[HD];
    __shared__ float ps[SC];
    int t = threadIdx.x;
    ((float4*)qs)[t] = ((const float4*)(g_q + (size_t)b * HD))[t];
    __syncthreads();
    int w = t >> 5, lane = t & 31;
    float cb = g_cb[b];
    unsigned long long qr[16];
    #pragma unroll
    for (int i = 0; i < 8; i++) {
        ulonglong2 qq = *(const ulonglong2*)&qs[(lane + i * 32) * 4];
        qr[2 * i] = qq.x; qr[2 * i + 1] = qq.y;
    }
    #pragma unroll
    for (int rr = 0; rr < 8; rr++) {
        int s = s0 + rr * 8 + w;
        const float* e = enc + ((size_t)b * SS + s) * HD;
        unsigned long long a0 = 0ull, a1 = 0ull;
        #pragma unroll
        for (int i = 0; i < 8; i++) {
            ulonglong2 ee = *(const ulonglong2*)&e[(lane + i * 32) * 4];
            asm("fma.rn.f32x2 %0, %1, %2, %0;" : "+l"(a0) : "l"(ee.x), "l"(qr[2 * i]));
            asm("fma.rn.f32x2 %0, %1, %2, %0;" : "+l"(a1) : "l"(ee.y), "l"(qr[2 * i + 1]));
        }
        float l0, h0_, l1, h1_;
        asm("mov.b64 {%0, %1}, %2;" : "=f"(l0), "=f"(h0_) : "l"(a0));
        asm("mov.b64 {%0, %1}, %2;" : "=f"(l1), "=f"(h1_) : "l"(a1));
        float sum = (l0 + h0_) + (l1 + h1_);
        #pragma unroll
        for (int o = 16; o > 0; o >>= 1) sum += __shfl_xor_sync(0xffffffffu, sum, o);
        if (lane == 0) {
            float val = sum + cb;
            ps[rr * 8 + w] = val;
            g_scores[(size_t)b * SS + s] = val;
        }
    }
    __syncthreads();
    if (t < 32) {
        float v0 = ps[t], v1 = ps[t + 32];
        float m = fmaxf(v0, v1);
        #pragma unroll
        for (int o = 16; o > 0; o >>= 1) m = fmaxf(m, __shfl_xor_sync(0xffffffffu, m, o));
        float p0 = expf(v0 - m), p1 = expf(v1 - m);
        float l = p0 + p1;
        #pragma unroll
        for (int o = 16; o > 0; o >>= 1) l += __shfl_xor_sync(0xffffffffu, l, o);
        ps[t] = p0; ps[t + 32] = p1;
        if (t == 0) { g_pm[b * NCH + ch] = m; g_pl[b * NCH + ch] = l; }
    }
    __syncthreads();
    float4 acc = {0, 0, 0, 0};
    const float* eb = enc + ((size_t)b * SS + s0) * HD;
    #pragma unroll 8
    for (int s = 0; s < SC; s++) {
        float p = ps[s];
        float4 ev = *(const float4*)(eb + (size_t)s * HD + t * 4);
        acc.x += p * ev.x; acc.y += p * ev.y; acc.z += p * ev.z; acc.w += p * ev.w;
    }
    *(float4*)(g_pctx + ((size_t)(b * NCH + ch)) * HD + t * 4) = acc;
}

// ---------------- 7: combine attention partials -> context + catT ----------------
__global__ __launch_bounds__(256) void k_att_reduce(float* __restrict__ ctx_out) {
    int b = blockIdx.x, t = threadIdx.x;
    __shared__ float wc[NCH];
    __shared__ float MZ[2];
    if (t < 32) {
        float m = g_pm[b * NCH + t];
        float M = m;
        #pragma unroll
        for (int o = 16; o > 0; o >>= 1) M = fmaxf(M, __shfl_xor_sync(0xffffffffu, M, o));
        float e = expf(m - M);
        float z = g_pl[b * NCH + t] * e;
        #pragma unroll
        for (int o = 16; o > 0; o >>= 1) z += __shfl_xor_sync(0xffffffffu, z, o);
        wc[t] = e;
        if (t == 0) { MZ[0] = M; MZ[1] = z; g_MZ[b * 2] = M; g_MZ[b * 2 + 1] = z; }
    }
    __syncthreads();
    float invZ = 1.0f / MZ[1];
    float4 acc = {0, 0, 0, 0};
    #pragma unroll 4
    for (int c = 0; c < NCH; c++) {
        float s = wc[c];
        float4 v = *(const float4*)(g_pctx + ((size_t)(b * NCH + c)) * HD + t * 4);
        acc.x += s * v.x; acc.y += s * v.y; acc.z += s * v.z; acc.w += s * v.w;
    }
    acc.x *= invZ; acc.y *= invZ; acc.z *= invZ; acc.w *= invZ;
    *(float4*)(ctx_out + (size_t)b * HD + t * 4) = acc;
    int h = t * 4;
    g_catT[(HD + h + 0) * BB + b] = acc.x; g_catT[(HD + h + 1) * BB + b] = acc.y;
    g_catT[(HD + h + 2) * BB + b] = acc.z; g_catT[(HD + h + 3) * BB + b] = acc.w;
    float4 h1v = *(const float4*)(g_h1 + (size_t)b * HD + t * 4);
    g_catT[(h + 0) * BB + b] = h1v.x; g_catT[(h + 1) * BB + b] = h1v.y;
    g_catT[(h + 2) * BB + b] = h1v.z; g_catT[(h + 3) * BB + b] = h1v.w;
}

// ---------------- 8: normalized attention weights ----------------
__global__ void k_attn_out(float* __restrict__ attn_out) {
    int idx = blockIdx.x * 256 + threadIdx.x;   // BB*SS
    int b = idx >> 11;
    float M = g_MZ[b * 2], Z = g_MZ[b * 2 + 1];
    attn_out[idx] = expf(g_scores[idx] - M) / Z;
}

// ---------------- 9: combine logits softmax partials ----------------
__global__ void k_lstats() {
    int b = blockIdx.x, t = threadIdx.x;   // 256 threads
    float m = -3.0e38f, s = 0.0f;
    if (t < LBLK) { m = g_lm[t * BB + b]; s = g_ls[t * BB + b]; }
    int lane = t & 31, w = t >> 5;
    #pragma unroll
    for (int o = 16; o > 0; o >>= 1) {
        float mo = __shfl_xor_sync(0xffffffffu, m, o);
        float so = __shfl_xor_sync(0xffffffffu, s, o);
        float M = fmaxf(m, mo);
        s = s * expf(m - M) + so * expf(mo - M);
        m = M;
    }
    __shared__ float sm[8], ss[8];
    if (lane == 0) { sm[w] = m; ss[w] = s; }
    __syncthreads();
    if (t == 0) {
        float M = sm[0], S = ss[0];
        #pragma unroll
        for (int i = 1; i < 8; i++) {
            float M2 = fmaxf(M, sm[i]);
            S = S * expf(M - M2) + ss[i] * expf(sm[i] - M2);
            M = M2;
        }
        g_MZl[b * 2] = M; g_MZl[b * 2 + 1] = S;
    }
}

// ---------------- 10: write output softmax ----------------
__global__ void k_wout(float* __restrict__ out) {
    int i4 = blockIdx.x * 256 + threadIdx.x;   // 256000 float4s
    int idx = i4 * 4;
    int b = idx / VV;
    float M = g_MZl[b * 2];
    float invZ = 1.0f / g_MZl[b * 2 + 1];
    float4 l = *(const float4*)(g_logits + idx);
    float4 o;
    o.x = expf(l.x - M) * invZ; o.y = expf(l.y - M) * invZ;
    o.z = expf(l.z - M) * invZ; o.w = expf(l.w - M) * invZ;
    *(float4*)(out + idx) = o;
}

// ---------------- launch ----------------
extern "C" void kernel_launch(void* const* d_in, const int* in_sizes, int n_in,
                              void* d_out, int out_size) {
    const int*   ids   = (const int*)d_in[0];
    const float* lctx  = (const float*)d_in[1];
    const float* hid   = (const float*)d_in[2];
    const float* enc   = (const float*)d_in[3];
    const float* emb   = (const float*)d_in[4];
    const float* Wattn = (const float*)d_in[5];
    const float* battn = (const float*)d_in[6];
    const float* Wih0  = (const float*)d_in[7];
    const float* Whh0  = (const float*)d_in[8];
    const float* bih0  = (const float*)d_in[9];
    const float* bhh0  = (const float*)d_in[10];
    const float* Wih1  = (const float*)d_in[11];
    const float* Whh1  = (const float*)d_in[12];
    const float* bih1  = (const float*)d_in[13];
    const float* bhh1  = (const float*)d_in[14];
    const float* Wout  = (const float*)d_in[15];
    const float* bout  = (const float*)d_in[16];

    float* out = (float*)d_out;
    float* out_probs = out;                               // [B,V]
    float* out_ctx   = out + (size_t)BB * VV;             // [1,B,H]
    float* out_hid   = out_ctx + (size_t)BB * HD;         // [L,B,H]
    float* out_attn  = out_hid + (size_t)2 * BB * HD;     // [B,1,S]

    float *p_xT, *p_hT, *p_h0T, *p_h1, *p_h1T, *p_catT;
    float *p_pgi, *p_pgh, *p_pq, *p_logits, *p_lm, *p_ls;
    cudaGetSymbolAddress((void**)&p_xT,     g_xT);
    cudaGetSymbolAddress((void**)&p_hT,     g_hT);
    cudaGetSymbolAddress((void**)&p_h0T,    g_h0T);
    cudaGetSymbolAddress((void**)&p_h1,     g_h1);
    cudaGetSymbolAddress((void**)&p_h1T,    g_h1T);
    cudaGetSymbolAddress((void**)&p_catT,   g_catT);
    cudaGetSymbolAddress((void**)&p_pgi,    g_pgi);
    cudaGetSymbolAddress((void**)&p_pgh,    g_pgh);
    cudaGetSymbolAddress((void**)&p_pq,     g_pq);
    cudaGetSymbolAddress((void**)&p_logits, g_logits);
    cudaGetSymbolAddress((void**)&p_lm,     g_lm);
    cudaGetSymbolAddress((void**)&p_ls,     g_ls);

    // 1. inputs -> transposed layouts
    k_embed<<<BB, 256>>>(ids, emb, lctx);
    k_transpose<<<dim3(HD / 32, 2), dim3(32, 32)>>>(hid);
    // 2. GRU layer 0
    k_gemm<<<dim3(G3/128, SK), 128>>>(p_xT, Wih0, nullptr, p_pgi, G3, 2*HD, 0, (2*HD)/SK, 0, nullptr, nullptr);
    k_gemm<<<dim3(G3/128, SK), 128>>>(p_hT, Whh0, nullptr, p_pgh, G3, HD,   0, HD/SK,     0, nullptr, nullptr);
    k_combine<<<(BB*HD)/256, 256>>>(bih0, bhh0, hid, p_h0T, out_hid, nullptr);
    // 3. GRU layer 1
    k_gemm<<<dim3(G3/128, SK), 128>>>(p_h0T,            Wih1, nullptr, p_pgi, G3, HD, 0, HD/SK, 0, nullptr, nullptr);
    k_gemm<<<dim3(G3/128, SK), 128>>>(p_hT + HD*BB,     Whh1, nullptr, p_pgh, G3, HD, 0, HD/SK, 0, nullptr, nullptr);
    k_combine<<<(BB*HD)/256, 256>>>(bih1, bhh1, hid + BB*HD, p_h1T, out_hid + BB*HD, p_h1);
    // 4. q = h1 @ W_attn (+ cb)
    k_gemm<<<dim3(HD/128, SK), 128>>>(p_h1T, Wattn, nullptr, p_pq, HD, HD, 1, HD/SK, 0, nullptr, nullptr);
    k_qfin<<<BB, 256>>>(battn);
    // 5. attention
    k_scores_ctx<<<dim3(NCH, BB), 256>>>(enc);
    k_att_reduce<<<BB, 256>>>(out_ctx);
    k_attn_out<<<(BB*SS)/256, 256>>>(out_attn);
    // 6. logits GEMM (fused softmax stats) + output softmax
    k_gemm<<<dim3(LBLK, 1), 128>>>(p_catT, Wout, bout, p_logits, VV, 2*HD, 0, 2*HD, 1, p_lm, p_ls);
    k_lstats<<<BB, 256>>>();
    k_wout<<<(BB*VV/4)/256, 256>>>(out_probs);
}

// round 3
// speedup vs baseline: 1.7581x; 1.1241x over previous
#include <cuda_runtime.h>
#include <cstdint>
#include <cstddef>

#define HD 1024
#define BB 32
#define SS 2048
#define VV 32000
#define G3 3072
#define SC 16            // attention rows per chunk (smem-staged)
#define NCH (SS/SC)      // 128
#define SK 16            // k-split for GRU/q GEMMs
#define SKL 4            // k-split for logits GEMM
#define KT 64            // GEMM k-tile

// ---------------- scratch ----------------
__device__ float g_xT[2*HD*BB];
__device__ float g_hT[2*HD*BB];
__device__ float g_h0T[HD*BB];
__device__ float g_h1[BB*HD];
__device__ float g_h1T[HD*BB];
__device__ float g_catT[2*HD*BB];
__device__ float g_pgi[SK*BB*G3];
__device__ float g_pgh[SK*BB*G3];
__device__ float g_pq[SK*BB*HD];
__device__ float g_q[BB*HD];
__device__ float g_cb[BB];
__device__ float g_scores[BB*SS];
__device__ float g_pm[BB*NCH];
__device__ float g_pl[BB*NCH];
__device__ float g_wc[BB*NCH];
__device__ float g_pctx[(size_t)BB*NCH*HD];
__device__ float g_MZ[BB*2];
__device__ float g_plog[(size_t)SKL*BB*VV];
__device__ float g_logits[BB*VV];
__device__ float g_MZl[BB*2];

// ---------------- reductions ----------------
__device__ __forceinline__ float blockReduceSum256(float v) {
    __shared__ float s[8];
    int lane = threadIdx.x & 31, w = threadIdx.x >> 5;
    __syncthreads();
    #pragma unroll
    for (int o = 16; o > 0; o >>= 1) v += __shfl_xor_sync(0xffffffffu, v, o);
    if (lane == 0) s[w] = v;
    __syncthreads();
    if (w == 0) {
        float x = (lane < 8) ? s[lane] : 0.0f;
        #pragma unroll
        for (int o = 4; o > 0; o >>= 1) x += __shfl_xor_sync(0xffffffffu, x, o);
        if (lane == 0) s[0] = x;
    }
    __syncthreads();
    return s[0];
}

// ---------------- 1: embedding + concat -> xT (k-major) ----------------
__global__ void k_embed(const int* __restrict__ ids, const float* __restrict__ emb,
                        const float* __restrict__ lastctx) {
    int b = blockIdx.x, t = threadIdx.x;
    float4 e = ((const float4*)(emb + (size_t)ids[b] * HD))[t];
    float4 c = ((const float4*)(lastctx + (size_t)b * HD))[t];
    int h = t * 4;
    g_xT[(h+0)*BB + b] = e.x; g_xT[(h+1)*BB + b] = e.y;
    g_xT[(h+2)*BB + b] = e.z; g_xT[(h+3)*BB + b] = e.w;
    g_xT[(HD+h+0)*BB + b] = c.x; g_xT[(HD+h+1)*BB + b] = c.y;
    g_xT[(HD+h+2)*BB + b] = c.z; g_xT[(HD+h+3)*BB + b] = c.w;
}

// ---------------- 2: transpose hidden [L,B,H] -> [L,H,B] ----------------
__global__ void k_transpose(const float* __restrict__ in) {
    __shared__ float s[32][33];
    int l = blockIdx.y, h0 = blockIdx.x * 32;
    int tx = threadIdx.x, ty = threadIdx.y;
    s[ty][tx] = in[(size_t)l * BB * HD + (size_t)ty * HD + h0 + tx];
    __syncthreads();
    g_hT[(size_t)l * HD * BB + (size_t)(h0 + ty) * BB + tx] = s[tx][ty];
}

// ---------------- 3: skinny GEMM, dual-problem via blockIdx.z ----------------
// C[b,n] = sum_k XT[k][b]*W(n,k).  XT k-major [K][32].
// wt==0: W row-major [N][K]. wt==1: W(n,k)=W[k*N+n].
// gridDim.y = k-split count; partial sk writes at C + sk*BB*N; bias added at sk==0.
__global__ __launch_bounds__(128) void k_gemm(
    const float* __restrict__ XT0, const float* __restrict__ W0, float* __restrict__ C0, int kchunk0,
    const float* __restrict__ XT1, const float* __restrict__ W1, float* __restrict__ C1, int kchunk1,
    const float* __restrict__ bias, int N, int wt)
{
    const float* XT = (blockIdx.z == 0) ? XT0 : XT1;
    const float* W  = (blockIdx.z == 0) ? W0  : W1;
    float* C        = (blockIdx.z == 0) ? C0  : C1;
    int kchunk      = (blockIdx.z == 0) ? kchunk0 : kchunk1;
    int K           = kchunk * gridDim.y;

    __shared__ float Xs[32*66];
    __shared__ float Ws[128*64];
    int tid = threadIdx.x;
    int tn = tid & 15;
    int tb = tid >> 4;
    int n0 = blockIdx.x * 128;
    int kb = blockIdx.y * kchunk;

    unsigned long long acc[4][8];
    #pragma unroll
    for (int bi = 0; bi < 4; bi++)
        #pragma unroll
        for (int j = 0; j < 8; j++) acc[bi][j] = 0ull;

    for (int k0 = kb; k0 < kb + kchunk; k0 += KT) {
        #pragma unroll
        for (int r = 0; r < 16; r++) {
            int i = r * 128 + tid;
            int k = i >> 5, b = i & 31;
            Xs[b * 66 + k] = XT[(size_t)k0 * 32 + i];
        }
        if (!wt) {
            #pragma unroll
            for (int r = 0; r < 16; r++) {
                int i = r * 128 + tid;
                int n = i >> 4;
                int c = i & 15;
                float4 w4 = *(const float4*)(W + (size_t)(n0 + n) * K + k0 + c * 4);
                int cs = c ^ ((n >> 3) & 15);
                *(float4*)&Ws[n * 64 + cs * 4] = w4;
            }
        } else {
            for (int i = tid; i < 128 * KT; i += 128) {
                int n = i & 127, k = i >> 7;
                int cs = (k >> 2) ^ ((n >> 3) & 15);
                Ws[n * 64 + cs * 4 + (k & 3)] = W[(size_t)(k0 + k) * N + n0 + n];
            }
        }
        __syncthreads();
        #pragma unroll 4
        for (int kk = 0; kk < KT; kk += 4) {
            int csw = ((kk >> 2) ^ tn) * 4;
            unsigned long long x01[4], x23[4];
            #pragma unroll
            for (int bi = 0; bi < 4; bi++) {
                const float* xp = &Xs[(tb * 4 + bi) * 66 + kk];
                x01[bi] = *(const unsigned long long*)(xp);
                x23[bi] = *(const unsigned long long*)(xp + 2);
            }
            #pragma unroll
            for (int j = 0; j < 8; j++) {
                ulonglong2 w = *(const ulonglong2*)&Ws[(tn * 8 + j) * 64 + csw];
                #pragma unroll
                for (int bi = 0; bi < 4; bi++)
                    asm("fma.rn.f32x2 %0, %1, %2, %0;" : "+l"(acc[bi][j]) : "l"(x01[bi]), "l"(w.x));
                #pragma unroll
                for (int bi = 0; bi < 4; bi++)
                    asm("fma.rn.f32x2 %0, %1, %2, %0;" : "+l"(acc[bi][j]) : "l"(x23[bi]), "l"(w.y));
            }
        }
        __syncthreads();
    }

    size_t cbase = (size_t)blockIdx.y * BB * N;
    float v[4][8];
    #pragma unroll
    for (int j = 0; j < 8; j++) {
        float bv = (bias != nullptr && blockIdx.y == 0) ? bias[n0 + tn * 8 + j] : 0.0f;
        #pragma unroll
        for (int bi = 0; bi < 4; bi++) {
            float lo, hi;
            asm("mov.b64 {%0, %1}, %2;" : "=f"(lo), "=f"(hi) : "l"(acc[bi][j]));
            v[bi][j] = lo + hi + bv;
        }
    }
    #pragma unroll
    for (int bi = 0; bi < 4; bi++) {
        size_t off = cbase + (size_t)(tb * 4 + bi) * N + n0 + tn * 8;
        *(float4*)(C + off)     = make_float4(v[bi][0], v[bi][1], v[bi][2], v[bi][3]);
        *(float4*)(C + off + 4) = make_float4(v[bi][4], v[bi][5], v[bi][6], v[bi][7]);
    }
}

// ---------------- 4: GRU gate combine ----------------
__global__ void k_combine(const float* __restrict__ bih, const float* __restrict__ bhh,
                          const float* __restrict__ hprev, float* __restrict__ houtT,
                          float* __restrict__ hid_out, float* __restrict__ hout_row,
                          float* __restrict__ catT) {
    int idx = blockIdx.x * 256 + threadIdx.x;   // BB*HD
    int b = idx >> 10, h = idx & 1023;
    float gir = bih[h], giz = bih[HD + h], gin = bih[2 * HD + h];
    float ghr = bhh[h], ghz = bhh[HD + h], ghn = bhh[2 * HD + h];
    #pragma unroll
    for (int s = 0; s < SK; s++) {
        const float* pi = g_pgi + ((size_t)s * BB + b) * G3;
        const float* ph = g_pgh + ((size_t)s * BB + b) * G3;
        gir += pi[h]; giz += pi[HD + h]; gin += pi[2 * HD + h];
        ghr += ph[h]; ghz += ph[HD + h]; ghn += ph[2 * HD + h];
    }
    float r = 1.0f / (1.0f + expf(-(gir + ghr)));
    float z = 1.0f / (1.0f + expf(-(giz + ghz)));
    float n = tanhf(gin + r * ghn);
    float hn = (1.0f - z) * n + z * hprev[idx];
    houtT[h * BB + b] = hn;
    hid_out[idx] = hn;
    if (hout_row) hout_row[idx] = hn;
    if (catT) catT[h * BB + b] = hn;
}

// ---------------- 5: finalize q partials + cb = b_attn . h1 ----------------
__global__ void k_qfin(const float* __restrict__ b_attn) {
    int b = blockIdx.x, t = threadIdx.x;
    float4 acc = {0, 0, 0, 0};
    #pragma unroll
    for (int s = 0; s < SK; s++) {
        float4 v = *(const float4*)(g_pq + ((size_t)s * BB + b) * HD + t * 4);
        acc.x += v.x; acc.y += v.y; acc.z += v.z; acc.w += v.w;
    }
    *(float4*)(g_q + (size_t)b * HD + t * 4) = acc;
    float4 ba = *(const float4*)(b_attn + t * 4);
    float4 hv = *(const float4*)(g_h1 + (size_t)b * HD + t * 4);
    float p = ba.x * hv.x + ba.y * hv.y + ba.z * hv.z + ba.w * hv.w;
    p = blockReduceSum256(p);
    if (t == 0) g_cb[b] = p;
}

// ---------------- 6: attention chunk: smem-staged scores + partial ctx ----------------
// dynamic smem: qs[1024] | es[16][1028] | ps[16]
__global__ __launch_bounds__(256) void k_scores_ctx(const float* __restrict__ enc) {
    extern __shared__ float sm[];
    float* qs = sm;
    float* es = sm + 1024;           // 16 rows x 1028 floats (257 float4 stride)
    float* ps = sm + 1024 + 16 * 1028;
    int b = blockIdx.y, ch = blockIdx.x;
    int s0 = ch * SC;
    int t = threadIdx.x;
    ((float4*)qs)[t] = ((const float4*)(g_q + (size_t)b * HD))[t];
    // stage enc chunk: 4096 float4, linear coalesced
    const float4* eb = (const float4*)(enc + ((size_t)b * SS + s0) * HD);
    #pragma unroll
    for (int r = 0; r < 16; r++) {
        int i = r * 256 + t;
        int row = i >> 8, col = i & 255;
        ((float4*)es)[row * 257 + col] = eb[i];
    }
    __syncthreads();
    int w = t >> 5, lane = t & 31;
    float cb = g_cb[b];
    unsigned long long qr[16];
    #pragma unroll
    for (int i = 0; i < 8; i++) {
        ulonglong2 qq = *(const ulonglong2*)&qs[(lane + i * 32) * 4];
        qr[2 * i] = qq.x; qr[2 * i + 1] = qq.y;
    }
    // phase 1: 8 warps x 2 rows
    #pragma unroll
    for (int rr = 0; rr < 2; rr++) {
        int r = w * 2 + rr;
        const float* e = es + r * 1028;
        unsigned long long a0 = 0ull, a1 = 0ull;
        #pragma unroll
        for (int i = 0; i < 8; i++) {
            ulonglong2 ee = *(const ulonglong2*)&e[(lane + i * 32) * 4];
            asm("fma.rn.f32x2 %0, %1, %2, %0;" : "+l"(a0) : "l"(ee.x), "l"(qr[2 * i]));
            asm("fma.rn.f32x2 %0, %1, %2, %0;" : "+l"(a1) : "l"(ee.y), "l"(qr[2 * i + 1]));
        }
        float l0, h0_, l1, h1_;
        asm("mov.b64 {%0, %1}, %2;" : "=f"(l0), "=f"(h0_) : "l"(a0));
        asm("mov.b64 {%0, %1}, %2;" : "=f"(l1), "=f"(h1_) : "l"(a1));
        float sum = (l0 + h0_) + (l1 + h1_);
        #pragma unroll
        for (int o = 16; o > 0; o >>= 1) sum += __shfl_xor_sync(0xffffffffu, sum, o);
        if (lane == 0) {
            float val = sum + cb;
            ps[r] = val;
            g_scores[(size_t)b * SS + s0 + r] = val;
        }
    }
    __syncthreads();
    // phase 2: chunk stats (warp 0)
    if (t < 32) {
        float v = (t < SC) ? ps[t] : -3.0e38f;
        float m = v;
        #pragma unroll
        for (int o = 16; o > 0; o >>= 1) m = fmaxf(m, __shfl_xor_sync(0xffffffffu, m, o));
        float p = (t < SC) ? expf(v - m) : 0.0f;
        float l = p;
        #pragma unroll
        for (int o = 16; o > 0; o >>= 1) l += __shfl_xor_sync(0xffffffffu, l, o);
        if (t < SC) ps[t] = p;
        if (t == 0) { g_pm[b * NCH + ch] = m; g_pl[b * NCH + ch] = l; }
    }
    __syncthreads();
    // phase 3: partial context from smem
    float4 acc = {0, 0, 0, 0};
    #pragma unroll
    for (int s = 0; s < SC; s++) {
        float p = ps[s];
        float4 ev = ((const float4*)es)[s * 257 + t];
        acc.x += p * ev.x; acc.y += p * ev.y; acc.z += p * ev.z; acc.w += p * ev.w;
    }
    *(float4*)(g_pctx + ((size_t)(b * NCH + ch)) * HD + t * 4) = acc;
}

// ---------------- 7: global attn stats + chunk weights ----------------
__global__ void k_astat() {
    int b = blockIdx.x, t = threadIdx.x;   // 128 threads
    float m = g_pm[b * NCH + t];
    float l = g_pl[b * NCH + t];
    int lane = t & 31, w = t >> 5;
    float mm = m, ll = l;
    #pragma unroll
    for (int o = 16; o > 0; o >>= 1) {
        float mo = __shfl_xor_sync(0xffffffffu, mm, o);
        float lo = __shfl_xor_sync(0xffffffffu, ll, o);
        float M = fmaxf(mm, mo);
        ll = ll * expf(mm - M) + lo * expf(mo - M);
        mm = M;
    }
    __shared__ float sm_[4], sl_[4], MZ[2];
    if (lane == 0) { sm_[w] = mm; sl_[w] = ll; }
    __syncthreads();
    if (t == 0) {
        float M = sm_[0], Z = sl_[0];
        #pragma unroll
        for (int i = 1; i < 4; i++) {
            float M2 = fmaxf(M, sm_[i]);
            Z = Z * expf(M - M2) + sl_[i] * expf(sm_[i] - M2);
            M = M2;
        }
        MZ[0] = M; MZ[1] = Z;
        g_MZ[b * 2] = M; g_MZ[b * 2 + 1] = Z;
    }
    __syncthreads();
    g_wc[b * NCH + t] = expf(m - MZ[0]) / MZ[1];
}

// ---------------- 8: context = sum_ch wc*pctx  -> ctx_out + catT ----------------
__global__ __launch_bounds__(256) void k_act(float* __restrict__ ctx_out) {
    int b = blockIdx.x, g = blockIdx.y;           // g: 8 h-groups of 32 f4
    int t = threadIdx.x;
    int cg = t >> 5, i = t & 31;                  // cg: 8 chunk-subgroups
    int f4c = g * 32 + i;
    __shared__ float wcs[NCH];
    if (t < NCH) wcs[t] = g_wc[b * NCH + t];
    __syncthreads();
    float4 acc = {0, 0, 0, 0};
    #pragma unroll
    for (int c = cg; c < NCH; c += 8) {
        float s = wcs[c];
        float4 v = *(const float4*)(g_pctx + ((size_t)(b * NCH + c)) * HD + f4c * 4);
        acc.x += s * v.x; acc.y += s * v.y; acc.z += s * v.z; acc.w += s * v.w;
    }
    __shared__ float4 red[8][32];
    red[cg][i] = acc;
    __syncthreads();
    if (cg == 0) {
        #pragma unroll
        for (int r = 1; r < 8; r++) {
            float4 v = red[r][i];
            acc.x += v.x; acc.y += v.y; acc.z += v.z; acc.w += v.w;
        }
        int h = f4c * 4;
        *(float4*)(ctx_out + (size_t)b * HD + h) = acc;
        g_catT[(HD + h + 0) * BB + b] = acc.x;
        g_catT[(HD + h + 1) * BB + b] = acc.y;
        g_catT[(HD + h + 2) * BB + b] = acc.z;
        g_catT[(HD + h + 3) * BB + b] = acc.w;
    }
}

// ---------------- 9: normalized attention weights ----------------
__global__ void k_attn_out(float* __restrict__ attn_out) {
    int idx = blockIdx.x * 256 + threadIdx.x;
    int b = idx >> 11;
    float M = g_MZ[b * 2], Z = g_MZ[b * 2 + 1];
    attn_out[idx] = expf(g_scores[idx] - M) / Z;
}

// ---------------- 10: combine logits k-split partials ----------------
__global__ void k_lcombine() {
    int i4 = blockIdx.x * 256 + threadIdx.x;     // BB*VV/4 = 256000
    float4 a = *(const float4*)(g_plog + (size_t)i4 * 4);
    #pragma unroll
    for (int s = 1; s < SKL; s++) {
        float4 v = *(const float4*)(g_plog + (size_t)s * BB * VV + (size_t)i4 * 4);
        a.x += v.x; a.y += v.y; a.z += v.z; a.w += v.w;
    }
    *(float4*)(g_logits + (size_t)i4 * 4) = a;
}

// ---------------- 11: per-b softmax stats over V ----------------
__global__ void k_lstat() {
    int b = blockIdx.x, t = threadIdx.x;   // 256 threads
    const float* l = g_logits + (size_t)b * VV;
    float m = -3.0e38f, s = 0.0f;
    for (int i = t; i < VV; i += 256) {
        float v = l[i];
        if (v <= m) s += expf(v - m);
        else { s = s * expf(m - v) + 1.0f; m = v; }
    }
    int lane = t & 31, w = t >> 5;
    #pragma unroll
    for (int o = 16; o > 0; o >>= 1) {
        float mo = __shfl_xor_sync(0xffffffffu, m, o);
        float so = __shfl_xor_sync(0xffffffffu, s, o);
        float M = fmaxf(m, mo);
        s = s * expf(m - M) + so * expf(mo - M);
        m = M;
    }
    __shared__ float sm_[8], ss_[8];
    if (lane == 0) { sm_[w] = m; ss_[w] = s; }
    __syncthreads();
    if (t == 0) {
        float M = sm_[0], S = ss_[0];
        #pragma unroll
        for (int i = 1; i < 8; i++) {
            float M2 = fmaxf(M, sm_[i]);
            S = S * expf(M - M2) + ss_[i] * expf(sm_[i] - M2);
            M = M2;
        }
        g_MZl[b * 2] = M; g_MZl[b * 2 + 1] = S;
    }
}

// ---------------- 12: write output softmax ----------------
__global__ void k_wout(float* __restrict__ out) {
    int i4 = blockIdx.x * 256 + threadIdx.x;
    int idx = i4 * 4;
    int b = idx / VV;
    float M = g_MZl[b * 2];
    float invZ = 1.0f / g_MZl[b * 2 + 1];
    float4 l = *(const float4*)(g_logits + idx);
    float4 o;
    o.x = expf(l.x - M) * invZ; o.y = expf(l.y - M) * invZ;
    o.z = expf(l.z - M) * invZ; o.w = expf(l.w - M) * invZ;
    *(float4*)(out + idx) = o;
}

// ---------------- launch ----------------
extern "C" void kernel_launch(void* const* d_in, const int* in_sizes, int n_in,
                              void* d_out, int out_size) {
    const int*   ids   = (const int*)d_in[0];
    const float* lctx  = (const float*)d_in[1];
    const float* hid   = (const float*)d_in[2];
    const float* enc   = (const float*)d_in[3];
    const float* emb   = (const float*)d_in[4];
    const float* Wattn = (const float*)d_in[5];
    const float* battn = (const float*)d_in[6];
    const float* Wih0  = (const float*)d_in[7];
    const float* Whh0  = (const float*)d_in[8];
    const float* bih0  = (const float*)d_in[9];
    const float* bhh0  = (const float*)d_in[10];
    const float* Wih1  = (const float*)d_in[11];
    const float* Whh1  = (const float*)d_in[12];
    const float* bih1  = (const float*)d_in[13];
    const float* bhh1  = (const float*)d_in[14];
    const float* Wout  = (const float*)d_in[15];
    const float* bout  = (const float*)d_in[16];

    float* out = (float*)d_out;
    float* out_probs = out;
    float* out_ctx   = out + (size_t)BB * VV;
    float* out_hid   = out_ctx + (size_t)BB * HD;
    float* out_attn  = out_hid + (size_t)2 * BB * HD;

    float *p_xT, *p_hT, *p_h0T, *p_h1, *p_h1T, *p_catT, *p_pgi, *p_pgh, *p_pq, *p_plog;
    cudaGetSymbolAddress((void**)&p_xT,   g_xT);
    cudaGetSymbolAddress((void**)&p_hT,   g_hT);
    cudaGetSymbolAddress((void**)&p_h0T,  g_h0T);
    cudaGetSymbolAddress((void**)&p_h1,   g_h1);
    cudaGetSymbolAddress((void**)&p_h1T,  g_h1T);
    cudaGetSymbolAddress((void**)&p_catT, g_catT);
    cudaGetSymbolAddress((void**)&p_pgi,  g_pgi);
    cudaGetSymbolAddress((void**)&p_pgh,  g_pgh);
    cudaGetSymbolAddress((void**)&p_pq,   g_pq);
    cudaGetSymbolAddress((void**)&p_plog, g_plog);

    static int smem_set = 0;
    const int ATTN_SMEM = (1024 + 16 * 1028 + 16) * 4;
    if (!smem_set) {
        cudaFuncSetAttribute(k_scores_ctx, cudaFuncAttributeMaxDynamicSharedMemorySize, ATTN_SMEM);
        smem_set = 1;
    }

    // 1. inputs -> transposed layouts
    k_embed<<<BB, 256>>>(ids, emb, lctx);
    k_transpose<<<dim3(HD / 32, 2), dim3(32, 32)>>>(hid);
    // 2. GRU layer 0 (fused dual GEMM: z=0 Wih0/xT K=2048, z=1 Whh0/hT K=1024)
    k_gemm<<<dim3(G3/128, SK, 2), 128>>>(p_xT, Wih0, p_pgi, (2*HD)/SK,
                                         p_hT, Whh0, p_pgh, HD/SK, nullptr, G3, 0);
    k_combine<<<(BB*HD)/256, 256>>>(bih0, bhh0, hid, p_h0T, out_hid, nullptr, nullptr);
    // 3. GRU layer 1
    k_gemm<<<dim3(G3/128, SK, 2), 128>>>(p_h0T, Wih1, p_pgi, HD/SK,
                                         p_hT + HD*BB, Whh1, p_pgh, HD/SK, nullptr, G3, 0);
    k_combine<<<(BB*HD)/256, 256>>>(bih1, bhh1, hid + BB*HD, p_h1T, out_hid + BB*HD, p_h1, p_catT);
    // 4. q = h1 @ W_attn
    k_gemm<<<dim3(HD/128, SK, 1), 128>>>(p_h1T, Wattn, p_pq, HD/SK,
                                         p_h1T, Wattn, p_pq, HD/SK, nullptr, HD, 1);
    k_qfin<<<BB, 256>>>(battn);
    // 5. attention (single DRAM pass, smem-staged)
    k_scores_ctx<<<dim3(NCH, BB), 256, ATTN_SMEM>>>(enc);
    k_astat<<<BB, NCH>>>();
    k_act<<<dim3(BB, 8), 256>>>(out_ctx);
    k_attn_out<<<(BB*SS)/256, 256>>>(out_attn);
    // 6. logits GEMM (k-split x4) + softmax
    k_gemm<<<dim3(VV/128, SKL, 1), 128>>>(p_catT, Wout, p_plog, (2*HD)/SKL,
                                          p_catT, Wout, p_plog, (2*HD)/SKL, bout, VV, 0);
    k_lcombine<<<(BB*VV/4)/256, 256>>>();
    k_lstat<<<BB, 256>>>();
    k_wout<<<(BB*VV/4)/256, 256>>>(out_probs);
}